// round 6
// baseline (speedup 1.0000x reference)
#include <cuda_runtime.h>
#include <cstddef>
#include <cstdint>

// RoutingByAgreement: x[B,64,64] f32 -> v[B,64] f32, 3 iterations.
// 128-thread persistent CTAs (6/SM), double-buffered cp.async, approx FP.
// Thread t: g = t>>6 (0..1), d = t&63. Holds xB[j] = x[32g+j][d], j=0..31.
// Warp w covers one 32-wide d-half of group g=w>>1; partner warp is w^1.

#define FULLMASK 0xffffffffu

static __device__ __forceinline__ void cp_async16(void* smem_dst, const void* gsrc) {
    uint32_t s = (uint32_t)__cvta_generic_to_shared(smem_dst);
    asm volatile("cp.async.cg.shared.global [%0], [%1], 16;\n" :: "r"(s), "l"(gsrc));
}
static __device__ __forceinline__ void cp_async_commit() {
    asm volatile("cp.async.commit_group;\n" ::: "memory");
}
template<int N> static __device__ __forceinline__ void cp_async_wait() {
    asm volatile("cp.async.wait_group %0;\n" :: "n"(N) : "memory");
}
static __device__ __forceinline__ float frcp(float x) {
    float r; asm("rcp.approx.f32 %0, %1;" : "=f"(r) : "f"(x)); return r;
}
static __device__ __forceinline__ float frsq(float x) {
    float r; asm("rsqrt.approx.f32 %0, %1;" : "=f"(r) : "f"(x)); return r;
}

__global__ void __launch_bounds__(128, 6)
routing_kernel(const float* __restrict__ x, float* __restrict__ out, int B)
{
    __shared__ __align__(16) float buf[2][4096];  // 32 KB double buffer [64][64]
    __shared__ __align__(16) float spart[2 * 64]; // per-group partial s
    __shared__ __align__(16) float sAg[4 * 32];   // per-warp half-agreements
    __shared__ __align__(16) float se[64];        // exp(logits), unnormalized

    const int t = threadIdx.x;
    const int w = t >> 5;
    const int l = t & 31;
    const int g = t >> 6;
    const int d = t & 63;
    const int stride = gridDim.x;
    // lane's agreement row within its group: j = bitrev5(l)
    const int jrow = ((l & 1) << 4) | ((l & 2) << 2) | (l & 4)
                   | ((l & 8) >> 2) | ((l & 16) >> 4);
    const int seIdx = g * 32 + jrow;

    // prologue: prefetch first batch into buf[0] (128 B per thread)
    const int b0 = blockIdx.x;
    {
        const float* src = x + (size_t)b0 * 4096 + t * 32;
        float* dst = &buf[0][t * 32];
#pragma unroll
        for (int i = 0; i < 8; i++) cp_async16(dst + 4 * i, src + 4 * i);
    }
    cp_async_commit();

    int k = 0;
    for (int b = b0; b < B; b += stride, k ^= 1) {
        const int bn = b + stride;
        if (bn < B) {
            const float* src = x + (size_t)bn * 4096 + t * 32;
            float* dst = &buf[k ^ 1][t * 32];
#pragma unroll
            for (int i = 0; i < 8; i++) cp_async16(dst + 4 * i, src + 4 * i);
        }
        cp_async_commit();
        cp_async_wait<1>();            // current batch's group retired
        __syncthreads();

        // column slice into registers (bank = d mod 32 = lane: conflict-free)
        float xB[32];
        const float* bp = &buf[k][0];
#pragma unroll
        for (int j = 0; j < 32; j++) xB[j] = bp[(g * 32 + j) * 64 + d];
        __syncthreads();               // buf[k] free for the next prefetch

        float blog = 0.0f;             // per-lane logit for row (g, jrow)
        float v = 0.0f;

#pragma unroll
        for (int it = 0; it < 3; it++) {
            // ---- s-phase: p = sum_j e_j * xB_j (unnormalized weights) ----
            float p, zinv;
            if (it == 0) {
                float p0 = 0.f, p1 = 0.f, p2 = 0.f, p3 = 0.f;
#pragma unroll
                for (int i = 0; i < 8; i++) {
                    p0 += xB[i];      p1 += xB[8 + i];
                    p2 += xB[16 + i]; p3 += xB[24 + i];
                }
                p = (p0 + p1) + (p2 + p3);
                zinv = 1.0f / 64.0f;   // softmax(0) = 1/64
            } else {
                float zl = se[l] + se[l + 32];
#pragma unroll
                for (int off = 16; off > 0; off >>= 1)
                    zl += __shfl_xor_sync(FULLMASK, zl, off);
                zinv = frcp(zl);
                float q0 = 0.f, q1 = 0.f;
                const float4* e4 = reinterpret_cast<const float4*>(&se[g * 32]);
#pragma unroll
                for (int m = 0; m < 8; m += 2) {
                    float4 ea = e4[m], eb = e4[m + 1];   // broadcast LDS.128
                    q0 += ea.x * xB[4 * m]     + ea.y * xB[4 * m + 1]
                        + ea.z * xB[4 * m + 2] + ea.w * xB[4 * m + 3];
                    q1 += eb.x * xB[4 * m + 4] + eb.y * xB[4 * m + 5]
                        + eb.z * xB[4 * m + 6] + eb.w * xB[4 * m + 7];
                }
                p = q0 + q1;
            }
            spart[g * 64 + d] = p;
            __syncthreads();           // barrier A

            // ---- squash: both d-halves in-thread ({d, d^32} covers all 64) --
            const int dx = d ^ 32;
            float s0 = (spart[d]  + spart[64 + d])  * zinv;
            float s1 = (spart[dx] + spart[64 + dx]) * zinv;
            float nq = s0 * s0 + s1 * s1;
#pragma unroll
            for (int off = 16; off > 0; off >>= 1)
                nq += __shfl_xor_sync(FULLMASK, nq, off);
            float rn    = frsq(nq + 1e-20f);
            float nrm   = nq * rn;                         // sqrt(nq)
            float scale = nq * frcp((1.0f + nq) * (nrm + 1e-8f));
            v = s0 * scale;            // v for this thread's own d
            if (it == 2) break;        // uniform exit

            // ---- agreement: 5-step butterfly reduce-scatter of xB[j]*v over
            //      this warp's 32 d's -> per-warp HALF dot product per row ----
            float red[16];
            {
                bool hi = l & 1;
#pragma unroll
                for (int i = 0; i < 16; i++) {
                    float a0 = xB[i] * v, a1 = xB[i + 16] * v;
                    float send = hi ? a0 : a1;
                    float recv = __shfl_xor_sync(FULLMASK, send, 1);
                    red[i] = (hi ? a1 : a0) + recv;
                }
            }
#pragma unroll
            for (int kk = 1; kk < 5; kk++) {
                const int half = 16 >> kk;
                bool hi = (l >> kk) & 1;
#pragma unroll
                for (int i = 0; i < half; i++) {
                    float send = hi ? red[i] : red[i + half];
                    float recv = __shfl_xor_sync(FULLMASK, send, 1 << kk);
                    red[i] = (hi ? red[i + half] : red[i]) + recv;
                }
            }
            float agHalf = red[0];     // sum over this warp's 32 d's, row jrow
            sAg[w * 32 + jrow] = agHalf;   // jrow is a lane permutation: no conflict
            __syncthreads();           // barrier B

            // full agreement = my half + partner warp's (w^1) half
            blog += agHalf + sAg[(w ^ 1) * 32 + jrow];
            if (!(w & 1)) se[seIdx] = __expf(blog);   // one writer per row
            __syncthreads();           // barrier C (also protects spart WAR)
        }

        if (t < 64) out[(size_t)b * 64 + t] = v;   // g==0 covers all d
    }
}

extern "C" void kernel_launch(void* const* d_in, const int* in_sizes, int n_in,
                              void* d_out, int out_size)
{
    const float* x = (const float*)d_in[0];
    float* out = (float*)d_out;
    const int B = in_sizes[0] / 4096;
    int grid = 148 * 6;                // persistent: 6 CTAs per SM
    if (grid > B) grid = B;
    routing_kernel<<<grid, 128>>>(x, out, B);
}